// round 6
// baseline (speedup 1.0000x reference)
#include <cuda_runtime.h>
#include <cuda_bf16.h>
#include <cstdint>

// GRU encoder via mma.sync (HMMA bf16). 16 warps/CTA, 148 CTAs x 80 seqs.
// gh = h @ W_hh^T in 3 bf16 contributions (Ahi*Whi + Ahi*Wlo + Alo*Whi),
// merged into ONE K-loop reusing Whi fragments; Wlo LDGs pipelined.
// Exact fp32 h state in smem (stride 132). 2 syncthreads per step.

#define TT 24
#define NNN 184
#define SEQ 11776
#define M_CTA 80
#define GRIDX 148
#define NT 512
#define H_ELEMS 36175872ULL
#define HSTRIDE 132

// smem byte offsets
#define SM_WHI    0
#define SM_AHI    98304
#define SM_ALO    118784
#define SM_HST    139264            /* 80*132*4 = 42240 */
#define SM_W0     181504
#define SM_W1     183040
#define SM_BS     184576
#define SM_FCW    186624
#define SM_PMROW  187136
#define SM_XROW   187456
#define SM_CSROW  187776
#define SM_XPART  188096            /* 16*80*4 = 5120 */
#define SMEM_BYTES 193216

__device__ __align__(16) uint32_t g_wlofrag[16 * 32 * 8 * 8];  // 128KB

__device__ __forceinline__ uint32_t smem_u32(const void* p) {
    uint32_t a;
    asm("{ .reg .u64 t; cvta.to.shared.u64 t, %1; cvt.u32.u64 %0, t; }" : "=r"(a) : "l"(p));
    return a;
}

#define LDSM4(r0, r1, r2, r3, addr) \
    asm volatile("ldmatrix.sync.aligned.m8n8.x4.shared.b16 {%0,%1,%2,%3}, [%4];" \
        : "=r"(r0), "=r"(r1), "=r"(r2), "=r"(r3) : "r"(addr))
#define LDSM2(r0, r1, addr) \
    asm volatile("ldmatrix.sync.aligned.m8n8.x2.shared.b16 {%0,%1}, [%2];" \
        : "=r"(r0), "=r"(r1) : "r"(addr))

#define MMA16816(c, a, b) \
    asm volatile("mma.sync.aligned.m16n8k16.row.col.f32.bf16.bf16.f32 " \
        "{%0,%1,%2,%3}, {%4,%5,%6,%7}, {%8,%9}, {%0,%1,%2,%3};" \
        : "+f"((c)[0]), "+f"((c)[1]), "+f"((c)[2]), "+f"((c)[3]) \
        : "r"((a)[0]), "r"((a)[1]), "r"((a)[2]), "r"((a)[3]), \
          "r"((b)[0]), "r"((b)[1]))

__device__ __forceinline__ uint32_t packbf2(float x, float y) {
    return (uint32_t)__bfloat16_as_ushort(__float2bfloat16(x))
         | ((uint32_t)__bfloat16_as_ushort(__float2bfloat16(y)) << 16);
}
__device__ __forceinline__ float frcp(float x) {
    float y;
    asm("rcp.approx.f32 %0, %1;" : "=f"(y) : "f"(x));
    return y;
}

// ---- setup: pack Wlo = W - bf16(W) into per-thread fragment order ----
__global__ void pack_wlo_kernel(const float* __restrict__ Whh) {
    int t = blockIdx.x * blockDim.x + threadIdx.x;
    if (t >= 4096) return;
    int K = t & 7, l = (t >> 3) & 31, w = t >> 8;
#pragma unroll
    for (int s = 0; s < 3; s++) {
#pragma unroll
        for (int r = 0; r < 2; r++) {
            int tau = w + 16 * s;
            int j = 8 * tau + (l >> 2);
            int k0 = 16 * K + 8 * r + 2 * (l & 3);
            float w0 = Whh[j * 128 + k0], w1 = Whh[j * 128 + k0 + 1];
            float l0 = w0 - __bfloat162float(__float2bfloat16(w0));
            float l1 = w1 - __bfloat162float(__float2bfloat16(w1));
            g_wlofrag[t * 8 + 2 * s + r] = packbf2(l0, l1);
        }
    }
    g_wlofrag[t * 8 + 6] = 0u;
    g_wlofrag[t * 8 + 7] = 0u;
}

__global__ void __launch_bounds__(NT, 1)
gru_mma_kernel(const float* __restrict__ pm,
               const float* __restrict__ Wih,
               const float* __restrict__ Whh,
               const float* __restrict__ bih_g,
               const float* __restrict__ bhh_g,
               const float* __restrict__ fcw_g,
               const float* __restrict__ fcb_g,
               float* __restrict__ out)
{
    extern __shared__ char smem[];
    const uint32_t smb = smem_u32(smem);
    const int tid = threadIdx.x;
    const int lane = tid & 31;
    const int w = tid >> 5;
    const int bid80 = blockIdx.x * M_CTA;

    float* w0s   = (float*)(smem + SM_W0);
    float* w1s   = (float*)(smem + SM_W1);
    float* bss   = (float*)(smem + SM_BS);
    float* fcws  = (float*)(smem + SM_FCW);
    float* pmrow = (float*)(smem + SM_PMROW);
    float* xrow  = (float*)(smem + SM_XROW);
    int*   csrow = (int*)  (smem + SM_CSROW);
    float* xpart = (float*)(smem + SM_XPART);
    float* hst   = (float*)(smem + SM_HST);

    // stage Whi (bf16, swizzled): addr = j*256 + (((k>>3)^(j&7))<<4) + (k&7)*2
    {
        const float4* Wg = (const float4*)Whh;
        for (int v = tid; v < 384 * 32; v += NT) {
            int j = v >> 5, k4 = (v & 31) * 4;
            float4 wv = Wg[v];
            uint32_t off = (uint32_t)(j * 256 + ((((k4 >> 3) ^ (j & 7))) << 4) + (k4 & 7) * 2);
            *(uint2*)(smem + SM_WHI + off) =
                make_uint2(packbf2(wv.x, wv.y), packbf2(wv.z, wv.w));
        }
    }
    for (int v = tid; v < 40960 / 8; v += NT)
        ((uint2*)(smem + SM_AHI))[v] = make_uint2(0u, 0u);
    for (int v = tid; v < 80 * HSTRIDE; v += NT)
        hst[v] = 0.f;

    for (int i = tid; i < 384; i += NT) { w0s[i] = Wih[2 * i]; w1s[i] = Wih[2 * i + 1]; }
    if (tid < 128) {
        bss[tid]       = bih_g[tid]       + bhh_g[tid];         // r
        bss[128 + tid] = bih_g[128 + tid] + bhh_g[128 + tid];   // z
        bss[256 + tid] = bih_g[256 + tid];                       // i_n bias
        bss[384 + tid] = bhh_g[256 + tid];                       // h_n bias
        fcws[tid] = fcw_g[tid];
    }
    if (tid < M_CTA) {
        int s = bid80 + tid;
        bool v = s < SEQ;
        int ss = v ? s : 0;
        int b = ss / NNN, n = ss % NNN;
        csrow[tid] = b * TT * NNN + n;
        pmrow[tid] = v ? pm[b * TT * NNN + n] : 0.f;
        xrow[tid] = 0.f;
    }
    __syncthreads();

    // lane roles
    const int lx7 = lane & 7;
    const int rA  = (lane & 7) + ((lane >> 3) & 1) * 8;
    const int cA  = lane >> 4;
    const int cB  = (lane >> 3) & 1;
    const int q   = lane >> 2, p4 = lane & 3;

    const uint32_t wA4 = smb + SM_WHI
        + (uint32_t)((8 * w + (lane & 7) + (((lane >> 4) & 1) << 7)) * 256);
    const uint32_t wA2 = smb + SM_WHI
        + (uint32_t)((8 * w + 256 + (lane & 7)) * 256);
    uint32_t aAddr[5];
#pragma unroll
    for (int mt = 0; mt < 5; mt++)
        aAddr[mt] = smb + (uint32_t)((16 * mt + rA) * 256);

    const uint4* wloP = (const uint4*)(g_wlofrag) + (size_t)((w * 32 + lane) * 8) * 2;
    const float fcb = fcb_g[0];
    const int c0 = 8 * w + 2 * p4;

    for (int t = 0; t < TT; t++) {
        float acc[3][5][4];
#pragma unroll
        for (int g = 0; g < 3; g++)
#pragma unroll
            for (int mt = 0; mt < 5; mt++)
#pragma unroll
                for (int e = 0; e < 4; e++) acc[g][mt][e] = 0.f;

        // merged MMA loop: per K — Ahi x Whi, Ahi x Wlo, Alo x Whi
        uint4 pf1 = __ldg(wloP);
        uint2 pf2 = __ldg((const uint2*)(wloP + 1));
#pragma unroll
        for (int K = 0; K < 8; K++) {
            uint32_t bl[3][2];
            bl[0][0] = pf1.x; bl[0][1] = pf1.y;
            bl[1][0] = pf1.z; bl[1][1] = pf1.w;
            bl[2][0] = pf2.x; bl[2][1] = pf2.y;
            if (K < 7) {   // prefetch next K (hidden under 45 MMAs)
                pf1 = __ldg(wloP + (K + 1) * 2);
                pf2 = __ldg((const uint2*)(wloP + (K + 1) * 2 + 1));
            }
            const uint32_t offA = (uint32_t)(((2 * K + cA) ^ lx7) << 4);
            const uint32_t offW = (uint32_t)(((2 * K + cB) ^ lx7) << 4);
            uint32_t bh[3][2];
            LDSM4(bh[0][0], bh[0][1], bh[1][0], bh[1][1], wA4 + offW);
            LDSM2(bh[2][0], bh[2][1], wA2 + offW);
            uint32_t a[5][4];
#pragma unroll
            for (int mt = 0; mt < 5; mt++)
                LDSM4(a[mt][0], a[mt][1], a[mt][2], a[mt][3],
                      aAddr[mt] + SM_AHI + offA);
#pragma unroll
            for (int g = 0; g < 3; g++)
#pragma unroll
                for (int mt = 0; mt < 5; mt++) {
                    MMA16816(acc[g][mt], a[mt], bh[g]);
                    MMA16816(acc[g][mt], a[mt], bl[g]);
                }
            // Alo pass reuses Whi fragments
#pragma unroll
            for (int mt = 0; mt < 5; mt++)
                LDSM4(a[mt][0], a[mt][1], a[mt][2], a[mt][3],
                      aAddr[mt] + SM_ALO + offA);
#pragma unroll
            for (int g = 0; g < 3; g++)
#pragma unroll
                for (int mt = 0; mt < 5; mt++)
                    MMA16816(acc[g][mt], a[mt], bh[g]);
        }
        __syncthreads();   // B1: A reads done; publishes xrow/pmrow from prev iter

        // ---- epilogue ----
        float w0r[2], w1r[2], br[2], w0z[2], w1z[2], bz[2],
              w0n[2], w1n[2], bi_n[2], bh_n[2], fc[2];
#pragma unroll
        for (int e = 0; e < 2; e++) {
            const int c = c0 + e;
            w0r[e] = w0s[c];       w1r[e] = w1s[c];       br[e] = bss[c];
            w0z[e] = w0s[128 + c]; w1z[e] = w1s[128 + c]; bz[e] = bss[128 + c];
            w0n[e] = w0s[256 + c]; w1n[e] = w1s[256 + c];
            bi_n[e] = bss[256 + c]; bh_n[e] = bss[384 + c];
            fc[e] = fcws[c];
        }

        float px[10];
#pragma unroll
        for (int i = 0; i < 10; i++) px[i] = 0.f;

#pragma unroll
        for (int mt = 0; mt < 5; mt++)
#pragma unroll
            for (int hf = 0; hf < 2; hf++) {
                const int row = 16 * mt + 8 * hf + q;
                const float xm = xrow[row], pv = pmrow[row];
                float2 ho2 = *(float2*)(hst + row * HSTRIDE + c0);
                const int r0i = hf * 2, r1i = hf * 2 + 1;

                const float gr0 = acc[0][mt][r0i] + fmaf(w0r[0], xm, fmaf(w1r[0], pv, br[0]));
                const float gr1 = acc[0][mt][r1i] + fmaf(w0r[1], xm, fmaf(w1r[1], pv, br[1]));
                const float gz0 = acc[1][mt][r0i] + fmaf(w0z[0], xm, fmaf(w1z[0], pv, bz[0]));
                const float gz1 = acc[1][mt][r1i] + fmaf(w0z[1], xm, fmaf(w1z[1], pv, bz[1]));
                // batched sigmoids: one rcp for 4 denominators
                const float dr0 = 1.f + __expf(-gr0);
                const float dr1 = 1.f + __expf(-gr1);
                const float dz0 = 1.f + __expf(-gz0);
                const float dz1 = 1.f + __expf(-gz1);
                const float m0 = dr0 * dr1, m1 = dz0 * dz1;
                const float rp = frcp(m0 * m1);
                const float r_0 = (dr1 * m1) * rp;
                const float r_1 = (dr0 * m1) * rp;
                const float z_0 = (m0 * dz1) * rp;
                const float z_1 = (m0 * dz0) * rp;

                const float a0 = fmaf(w0n[0], xm, fmaf(w1n[0], pv, bi_n[0]))
                               + r_0 * (acc[2][mt][r0i] + bh_n[0]);
                const float a1 = fmaf(w0n[1], xm, fmaf(w1n[1], pv, bi_n[1]))
                               + r_1 * (acc[2][mt][r1i] + bh_n[1]);
                // batched tanh: one rcp for both denominators
                const float dn0 = 1.f + __expf(2.f * a0);
                const float dn1 = 1.f + __expf(2.f * a1);
                const float rq = frcp(dn0 * dn1);
                const float nt0 = fmaf(-2.f, dn1 * rq, 1.f);
                const float nt1 = fmaf(-2.f, dn0 * rq, 1.f);

                const float hn0 = nt0 + z_0 * (ho2.x - nt0);
                const float hn1 = nt1 + z_1 * (ho2.y - nt1);
                px[mt * 2 + hf] = fmaf(hn0, fc[0], fmaf(hn1, fc[1], px[mt * 2 + hf]));

                *(float2*)(hst + row * HSTRIDE + c0) = make_float2(hn0, hn1);
                if (bid80 + row < SEQ)
                    *(float2*)(out + (size_t)(csrow[row] + t * NNN) * 128 + c0)
                        = make_float2(hn0, hn1);
                const float hh0 = __bfloat162float(__float2bfloat16(hn0));
                const float hh1 = __bfloat162float(__float2bfloat16(hn1));
                const uint32_t aoff = (uint32_t)(row * 256 + ((w ^ q) << 4) + 4 * p4);
                *(uint32_t*)(smem + SM_AHI + aoff) = packbf2(hn0, hn1);
                *(uint32_t*)(smem + SM_ALO + aoff) = packbf2(hn0 - hh0, hn1 - hh1);
            }

        // fc partials: sum over p4 lanes, stash per-warp
#pragma unroll
        for (int rr = 0; rr < 10; rr++) {
            float v = px[rr];
            v += __shfl_xor_sync(0xFFFFFFFFu, v, 1);
            v += __shfl_xor_sync(0xFFFFFFFFu, v, 2);
            if (p4 == 0)
                xpart[w * 80 + 16 * (rr >> 1) + 8 * (rr & 1) + q] = v;
        }
        __syncthreads();   // B2: A writes + xpart visible

        // x_{t+1}; published to other threads by next iteration's B1
        if (tid < M_CTA) {
            float sx = fcb;
#pragma unroll
            for (int ww = 0; ww < 16; ww++) sx += xpart[ww * 80 + tid];
            xrow[tid] = sx;
            const int s = bid80 + tid;
            const bool v = s < SEQ;
            if (t + 1 < TT) pmrow[tid] = v ? pm[csrow[tid] + (t + 1) * NNN] : 0.f;
            if (t == TT - 1 && v) out[H_ELEMS + (size_t)s] = sx;
        }
    }
}

extern "C" void kernel_launch(void* const* d_in, const int* in_sizes, int n_in,
                              void* d_out, int out_size) {
    (void)in_sizes; (void)n_in; (void)out_size;
    const float* pm  = (const float*)d_in[0];
    const float* Wih = (const float*)d_in[1];
    const float* Whh = (const float*)d_in[2];
    const float* bih = (const float*)d_in[3];
    const float* bhh = (const float*)d_in[4];
    const float* fcw = (const float*)d_in[5];
    const float* fcb = (const float*)d_in[6];
    float* out = (float*)d_out;

    pack_wlo_kernel<<<16, 256>>>(Whh);
    cudaFuncSetAttribute(gru_mma_kernel,
                         cudaFuncAttributeMaxDynamicSharedMemorySize,
                         SMEM_BYTES);
    gru_mma_kernel<<<GRIDX, NT, SMEM_BYTES>>>(
        pm, Wih, Whh, bih, bhh, fcw, fcb, out);
}

// round 7
// speedup vs baseline: 1.5022x; 1.5022x over previous
#include <cuda_runtime.h>
#include <cuda_bf16.h>
#include <cstdint>

// GRU encoder via mma.sync (HMMA bf16). 16 warps/CTA, 148 CTAs x 80 seqs.
// gh = h @ W_hh^T in 3 bf16 passes (Ahi*Whi + Ahi*Wlo + Alo*Whi).
// R5 two-pass loop structure (no merge -> no spills) + pipelined Wlo LDG,
// batched-MUFU epilogue, 2 syncthreads/step.

#define TT 24
#define NNN 184
#define SEQ 11776
#define M_CTA 80
#define GRIDX 148
#define NT 512
#define H_ELEMS 36175872ULL
#define HSTRIDE 132

// smem byte offsets
#define SM_WHI    0
#define SM_AHI    98304
#define SM_ALO    118784
#define SM_HST    139264            /* 80*132*4 = 42240 */
#define SM_W0     181504
#define SM_W1     183040
#define SM_BS     184576
#define SM_FCW    186624
#define SM_PMROW  187136
#define SM_XROW   187456
#define SM_CSROW  187776
#define SM_XPART  188096            /* 16*80*4 = 5120 */
#define SMEM_BYTES 193216

__device__ __align__(16) uint32_t g_wlofrag[16 * 32 * 8 * 8];  // 128KB

__device__ __forceinline__ uint32_t smem_u32(const void* p) {
    uint32_t a;
    asm("{ .reg .u64 t; cvta.to.shared.u64 t, %1; cvt.u32.u64 %0, t; }" : "=r"(a) : "l"(p));
    return a;
}

#define LDSM4(r0, r1, r2, r3, addr) \
    asm volatile("ldmatrix.sync.aligned.m8n8.x4.shared.b16 {%0,%1,%2,%3}, [%4];" \
        : "=r"(r0), "=r"(r1), "=r"(r2), "=r"(r3) : "r"(addr))
#define LDSM2(r0, r1, addr) \
    asm volatile("ldmatrix.sync.aligned.m8n8.x2.shared.b16 {%0,%1}, [%2];" \
        : "=r"(r0), "=r"(r1) : "r"(addr))

#define MMA16816(c, a, b) \
    asm volatile("mma.sync.aligned.m16n8k16.row.col.f32.bf16.bf16.f32 " \
        "{%0,%1,%2,%3}, {%4,%5,%6,%7}, {%8,%9}, {%0,%1,%2,%3};" \
        : "+f"((c)[0]), "+f"((c)[1]), "+f"((c)[2]), "+f"((c)[3]) \
        : "r"((a)[0]), "r"((a)[1]), "r"((a)[2]), "r"((a)[3]), \
          "r"((b)[0]), "r"((b)[1]))

__device__ __forceinline__ uint32_t packbf2(float x, float y) {
    return (uint32_t)__bfloat16_as_ushort(__float2bfloat16(x))
         | ((uint32_t)__bfloat16_as_ushort(__float2bfloat16(y)) << 16);
}
__device__ __forceinline__ float frcp(float x) {
    float y;
    asm("rcp.approx.f32 %0, %1;" : "=f"(y) : "f"(x));
    return y;
}

// ---- setup: pack Wlo = W - bf16(W) into per-thread fragment order ----
__global__ void pack_wlo_kernel(const float* __restrict__ Whh) {
    int t = blockIdx.x * blockDim.x + threadIdx.x;
    if (t >= 4096) return;
    int K = t & 7, l = (t >> 3) & 31, w = t >> 8;
#pragma unroll
    for (int s = 0; s < 3; s++) {
#pragma unroll
        for (int r = 0; r < 2; r++) {
            int tau = w + 16 * s;
            int j = 8 * tau + (l >> 2);
            int k0 = 16 * K + 8 * r + 2 * (l & 3);
            float w0 = Whh[j * 128 + k0], w1 = Whh[j * 128 + k0 + 1];
            float l0 = w0 - __bfloat162float(__float2bfloat16(w0));
            float l1 = w1 - __bfloat162float(__float2bfloat16(w1));
            g_wlofrag[t * 8 + 2 * s + r] = packbf2(l0, l1);
        }
    }
    g_wlofrag[t * 8 + 6] = 0u;
    g_wlofrag[t * 8 + 7] = 0u;
}

__global__ void __launch_bounds__(NT, 1)
gru_mma_kernel(const float* __restrict__ pm,
               const float* __restrict__ Wih,
               const float* __restrict__ Whh,
               const float* __restrict__ bih_g,
               const float* __restrict__ bhh_g,
               const float* __restrict__ fcw_g,
               const float* __restrict__ fcb_g,
               float* __restrict__ out)
{
    extern __shared__ char smem[];
    const uint32_t smb = smem_u32(smem);
    const int tid = threadIdx.x;
    const int lane = tid & 31;
    const int w = tid >> 5;
    const int bid80 = blockIdx.x * M_CTA;

    float* w0s   = (float*)(smem + SM_W0);
    float* w1s   = (float*)(smem + SM_W1);
    float* bss   = (float*)(smem + SM_BS);
    float* fcws  = (float*)(smem + SM_FCW);
    float* pmrow = (float*)(smem + SM_PMROW);
    float* xrow  = (float*)(smem + SM_XROW);
    int*   csrow = (int*)  (smem + SM_CSROW);
    float* xpart = (float*)(smem + SM_XPART);
    float* hst   = (float*)(smem + SM_HST);

    // stage Whi (bf16, swizzled): addr = j*256 + (((k>>3)^(j&7))<<4) + (k&7)*2
    {
        const float4* Wg = (const float4*)Whh;
        for (int v = tid; v < 384 * 32; v += NT) {
            int j = v >> 5, k4 = (v & 31) * 4;
            float4 wv = Wg[v];
            uint32_t off = (uint32_t)(j * 256 + ((((k4 >> 3) ^ (j & 7))) << 4) + (k4 & 7) * 2);
            *(uint2*)(smem + SM_WHI + off) =
                make_uint2(packbf2(wv.x, wv.y), packbf2(wv.z, wv.w));
        }
    }
    for (int v = tid; v < 40960 / 8; v += NT)
        ((uint2*)(smem + SM_AHI))[v] = make_uint2(0u, 0u);
    for (int v = tid; v < 80 * HSTRIDE; v += NT)
        hst[v] = 0.f;

    for (int i = tid; i < 384; i += NT) { w0s[i] = Wih[2 * i]; w1s[i] = Wih[2 * i + 1]; }
    if (tid < 128) {
        bss[tid]       = bih_g[tid]       + bhh_g[tid];         // r
        bss[128 + tid] = bih_g[128 + tid] + bhh_g[128 + tid];   // z
        bss[256 + tid] = bih_g[256 + tid];                       // i_n bias
        bss[384 + tid] = bhh_g[256 + tid];                       // h_n bias
        fcws[tid] = fcw_g[tid];
    }
    if (tid < M_CTA) {
        int s = bid80 + tid;
        bool v = s < SEQ;
        int ss = v ? s : 0;
        int b = ss / NNN, n = ss % NNN;
        csrow[tid] = b * TT * NNN + n;
        pmrow[tid] = v ? pm[b * TT * NNN + n] : 0.f;
        xrow[tid] = 0.f;
    }
    __syncthreads();

    // lane roles
    const int lx7 = lane & 7;
    const int rA  = (lane & 7) + ((lane >> 3) & 1) * 8;
    const int cA  = lane >> 4;
    const int cB  = (lane >> 3) & 1;
    const int q   = lane >> 2, p4 = lane & 3;

    const uint32_t wA4 = smb + SM_WHI
        + (uint32_t)((8 * w + (lane & 7) + (((lane >> 4) & 1) << 7)) * 256);
    const uint32_t wA2 = smb + SM_WHI
        + (uint32_t)((8 * w + 256 + (lane & 7)) * 256);
    uint32_t aAddr[5];
#pragma unroll
    for (int mt = 0; mt < 5; mt++)
        aAddr[mt] = smb + (uint32_t)((16 * mt + rA) * 256);

    const uint4* wloP = (const uint4*)(g_wlofrag) + (size_t)((w * 32 + lane) * 8) * 2;
    const float fcb = fcb_g[0];
    const int c0 = 8 * w + 2 * p4;

    for (int t = 0; t < TT; t++) {
        float acc[3][5][4];
#pragma unroll
        for (int g = 0; g < 3; g++)
#pragma unroll
            for (int mt = 0; mt < 5; mt++)
#pragma unroll
                for (int e = 0; e < 4; e++) acc[g][mt][e] = 0.f;

        // pass 1+2: Ahi x Whi + Ahi x Wlo (Wlo prefetched distance-1)
        uint4 pf1 = __ldg(wloP);
        uint2 pf2 = __ldg((const uint2*)(wloP + 1));
#pragma unroll
        for (int K = 0; K < 8; K++) {
            uint32_t bl[3][2];
            bl[0][0] = pf1.x; bl[0][1] = pf1.y;
            bl[1][0] = pf1.z; bl[1][1] = pf1.w;
            bl[2][0] = pf2.x; bl[2][1] = pf2.y;
            if (K < 7) {
                pf1 = __ldg(wloP + (K + 1) * 2);
                pf2 = __ldg((const uint2*)(wloP + (K + 1) * 2 + 1));
            }
            const uint32_t offA = (uint32_t)(((2 * K + cA) ^ lx7) << 4);
            uint32_t a[5][4];
#pragma unroll
            for (int mt = 0; mt < 5; mt++)
                LDSM4(a[mt][0], a[mt][1], a[mt][2], a[mt][3],
                      aAddr[mt] + SM_AHI + offA);
            const uint32_t offW = (uint32_t)(((2 * K + cB) ^ lx7) << 4);
            uint32_t bh[3][2];
            LDSM4(bh[0][0], bh[0][1], bh[1][0], bh[1][1], wA4 + offW);
            LDSM2(bh[2][0], bh[2][1], wA2 + offW);
#pragma unroll
            for (int g = 0; g < 3; g++)
#pragma unroll
                for (int mt = 0; mt < 5; mt++) {
                    MMA16816(acc[g][mt], a[mt], bh[g]);
                    MMA16816(acc[g][mt], a[mt], bl[g]);
                }
        }
        // pass 3: Alo x Whi
#pragma unroll
        for (int K = 0; K < 8; K++) {
            const uint32_t offA = (uint32_t)(((2 * K + cA) ^ lx7) << 4);
            uint32_t a[5][4];
#pragma unroll
            for (int mt = 0; mt < 5; mt++)
                LDSM4(a[mt][0], a[mt][1], a[mt][2], a[mt][3],
                      aAddr[mt] + SM_ALO + offA);
            const uint32_t offW = (uint32_t)(((2 * K + cB) ^ lx7) << 4);
            uint32_t bh[3][2];
            LDSM4(bh[0][0], bh[0][1], bh[1][0], bh[1][1], wA4 + offW);
            LDSM2(bh[2][0], bh[2][1], wA2 + offW);
#pragma unroll
            for (int g = 0; g < 3; g++)
#pragma unroll
                for (int mt = 0; mt < 5; mt++)
                    MMA16816(acc[g][mt], a[mt], bh[g]);
        }
        __syncthreads();   // B1: A reads done; also publishes xrow/pmrow(t)

        // ---- epilogue ----
        float w0r[2], w1r[2], br[2], w0z[2], w1z[2], bz[2],
              w0n[2], w1n[2], bi_n[2], bh_n[2], fc[2];
#pragma unroll
        for (int e = 0; e < 2; e++) {
            const int c = c0 + e;
            w0r[e] = w0s[c];       w1r[e] = w1s[c];       br[e] = bss[c];
            w0z[e] = w0s[128 + c]; w1z[e] = w1s[128 + c]; bz[e] = bss[128 + c];
            w0n[e] = w0s[256 + c]; w1n[e] = w1s[256 + c];
            bi_n[e] = bss[256 + c]; bh_n[e] = bss[384 + c];
            fc[e] = fcws[c];
        }

        float px[10];
#pragma unroll
        for (int i = 0; i < 10; i++) px[i] = 0.f;

#pragma unroll
        for (int mt = 0; mt < 5; mt++)
#pragma unroll
            for (int hf = 0; hf < 2; hf++) {
                const int row = 16 * mt + 8 * hf + q;
                const float xm = xrow[row], pv = pmrow[row];
                float2 ho2 = *(float2*)(hst + row * HSTRIDE + c0);
                const int r0i = hf * 2, r1i = hf * 2 + 1;

                const float gr0 = acc[0][mt][r0i] + fmaf(w0r[0], xm, fmaf(w1r[0], pv, br[0]));
                const float gr1 = acc[0][mt][r1i] + fmaf(w0r[1], xm, fmaf(w1r[1], pv, br[1]));
                const float gz0 = acc[1][mt][r0i] + fmaf(w0z[0], xm, fmaf(w1z[0], pv, bz[0]));
                const float gz1 = acc[1][mt][r1i] + fmaf(w0z[1], xm, fmaf(w1z[1], pv, bz[1]));
                // batched sigmoids: one rcp for 4 denominators
                const float dr0 = 1.f + __expf(-gr0);
                const float dr1 = 1.f + __expf(-gr1);
                const float dz0 = 1.f + __expf(-gz0);
                const float dz1 = 1.f + __expf(-gz1);
                const float m0 = dr0 * dr1, m1 = dz0 * dz1;
                const float rp = frcp(m0 * m1);
                const float r_0 = (dr1 * m1) * rp;
                const float r_1 = (dr0 * m1) * rp;
                const float z_0 = (m0 * dz1) * rp;
                const float z_1 = (m0 * dz0) * rp;

                const float a0 = fmaf(w0n[0], xm, fmaf(w1n[0], pv, bi_n[0]))
                               + r_0 * (acc[2][mt][r0i] + bh_n[0]);
                const float a1 = fmaf(w0n[1], xm, fmaf(w1n[1], pv, bi_n[1]))
                               + r_1 * (acc[2][mt][r1i] + bh_n[1]);
                // batched tanh: one rcp for both denominators
                const float dn0 = 1.f + __expf(2.f * a0);
                const float dn1 = 1.f + __expf(2.f * a1);
                const float rq = frcp(dn0 * dn1);
                const float nt0 = fmaf(-2.f, dn1 * rq, 1.f);
                const float nt1 = fmaf(-2.f, dn0 * rq, 1.f);

                const float hn0 = nt0 + z_0 * (ho2.x - nt0);
                const float hn1 = nt1 + z_1 * (ho2.y - nt1);
                px[mt * 2 + hf] = fmaf(hn0, fc[0], fmaf(hn1, fc[1], px[mt * 2 + hf]));

                *(float2*)(hst + row * HSTRIDE + c0) = make_float2(hn0, hn1);
                if (bid80 + row < SEQ)
                    *(float2*)(out + (size_t)(csrow[row] + t * NNN) * 128 + c0)
                        = make_float2(hn0, hn1);
                const float hh0 = __bfloat162float(__float2bfloat16(hn0));
                const float hh1 = __bfloat162float(__float2bfloat16(hn1));
                const uint32_t aoff = (uint32_t)(row * 256 + ((w ^ q) << 4) + 4 * p4);
                *(uint32_t*)(smem + SM_AHI + aoff) = packbf2(hn0, hn1);
                *(uint32_t*)(smem + SM_ALO + aoff) = packbf2(hn0 - hh0, hn1 - hh1);
            }

        // fc partials: sum over p4 lanes, stash per-warp
#pragma unroll
        for (int rr = 0; rr < 10; rr++) {
            float v = px[rr];
            v += __shfl_xor_sync(0xFFFFFFFFu, v, 1);
            v += __shfl_xor_sync(0xFFFFFFFFu, v, 2);
            if (p4 == 0)
                xpart[w * 80 + 16 * (rr >> 1) + 8 * (rr & 1) + q] = v;
        }
        __syncthreads();   // B2: A writes + xpart visible

        // x_{t+1}; published to other threads by next iteration's B1
        if (tid < M_CTA) {
            float sx = fcb;
#pragma unroll
            for (int ww = 0; ww < 16; ww++) sx += xpart[ww * 80 + tid];
            xrow[tid] = sx;
            const int s = bid80 + tid;
            const bool v = s < SEQ;
            if (t + 1 < TT) pmrow[tid] = v ? pm[csrow[tid] + (t + 1) * NNN] : 0.f;
            if (t == TT - 1 && v) out[H_ELEMS + (size_t)s] = sx;
        }
    }
}

extern "C" void kernel_launch(void* const* d_in, const int* in_sizes, int n_in,
                              void* d_out, int out_size) {
    (void)in_sizes; (void)n_in; (void)out_size;
    const float* pm  = (const float*)d_in[0];
    const float* Wih = (const float*)d_in[1];
    const float* Whh = (const float*)d_in[2];
    const float* bih = (const float*)d_in[3];
    const float* bhh = (const float*)d_in[4];
    const float* fcw = (const float*)d_in[5];
    const float* fcb = (const float*)d_in[6];
    float* out = (float*)d_out;

    pack_wlo_kernel<<<16, 256>>>(Whh);
    cudaFuncSetAttribute(gru_mma_kernel,
                         cudaFuncAttributeMaxDynamicSharedMemorySize,
                         SMEM_BYTES);
    gru_mma_kernel<<<GRIDX, NT, SMEM_BYTES>>>(
        pm, Wih, Whh, bih, bhh, fcw, fcb, out);
}

// round 8
// speedup vs baseline: 1.8890x; 1.2575x over previous
#include <cuda_runtime.h>
#include <cuda_fp16.h>
#include <cstdint>

// GRU encoder via mma.sync (HMMA fp16, f32 accum). 16 warps/CTA, 148 CTAs x 80 seqs.
// gh = h @ W_hh^T in 2 fp16 passes: Ahi*Whi + Ahi*Wlo  (hlo term dropped;
// fp16 has 11 mantissa bits -> per-step gh rel err ~2^-12, final ~3e-5).
// Exact fp32 h state in smem (stride 132). 2 syncthreads/step.

#define TT 24
#define NNN 184
#define SEQ 11776
#define M_CTA 80
#define GRIDX 148
#define NT 512
#define H_ELEMS 36175872ULL
#define HSTRIDE 132

// smem byte offsets
#define SM_WHI    0                 /* 384*256 = 98304 */
#define SM_AHI    98304             /* 80*256 padded to 128 rows = 32768 */
#define SM_HST    131072            /* 80*132*4 = 42240 */
#define SM_W0     173312
#define SM_W1     174848
#define SM_BS     176384
#define SM_FCW    178432
#define SM_PMROW  178944
#define SM_XROW   179264
#define SM_CSROW  179584
#define SM_XPART  179904            /* 16*80*4 = 5120 */
#define SMEM_BYTES 185024

__device__ __align__(16) uint32_t g_wlofrag[16 * 32 * 8 * 8];  // 128KB

__device__ __forceinline__ uint32_t smem_u32(const void* p) {
    uint32_t a;
    asm("{ .reg .u64 t; cvta.to.shared.u64 t, %1; cvt.u32.u64 %0, t; }" : "=r"(a) : "l"(p));
    return a;
}

#define LDSM4(r0, r1, r2, r3, addr) \
    asm volatile("ldmatrix.sync.aligned.m8n8.x4.shared.b16 {%0,%1,%2,%3}, [%4];" \
        : "=r"(r0), "=r"(r1), "=r"(r2), "=r"(r3) : "r"(addr))
#define LDSM2(r0, r1, addr) \
    asm volatile("ldmatrix.sync.aligned.m8n8.x2.shared.b16 {%0,%1}, [%2];" \
        : "=r"(r0), "=r"(r1) : "r"(addr))

#define MMA16816(c, a, b) \
    asm volatile("mma.sync.aligned.m16n8k16.row.col.f32.f16.f16.f32 " \
        "{%0,%1,%2,%3}, {%4,%5,%6,%7}, {%8,%9}, {%0,%1,%2,%3};" \
        : "+f"((c)[0]), "+f"((c)[1]), "+f"((c)[2]), "+f"((c)[3]) \
        : "r"((a)[0]), "r"((a)[1]), "r"((a)[2]), "r"((a)[3]), \
          "r"((b)[0]), "r"((b)[1]))

__device__ __forceinline__ uint32_t packh2(float x, float y) {
    uint32_t r;
    __half2 h = __floats2half2_rn(x, y);
    r = *(uint32_t*)&h;
    return r;
}
__device__ __forceinline__ float frcp(float x) {
    float y;
    asm("rcp.approx.f32 %0, %1;" : "=f"(y) : "f"(x));
    return y;
}

// ---- setup: pack Wlo = W - fp16(W) into per-thread fragment order ----
// thread t in [0,4096): K=t&7, l=(t>>3)&31, w=t>>8; tiles {w, w+16, w+32}.
__global__ void pack_wlo_kernel(const float* __restrict__ Whh) {
    int t = blockIdx.x * blockDim.x + threadIdx.x;
    if (t >= 4096) return;
    int K = t & 7, l = (t >> 3) & 31, w = t >> 8;
#pragma unroll
    for (int s = 0; s < 3; s++) {
#pragma unroll
        for (int r = 0; r < 2; r++) {
            int tau = w + 16 * s;
            int j = 8 * tau + (l >> 2);
            int k0 = 16 * K + 8 * r + 2 * (l & 3);
            float w0 = Whh[j * 128 + k0], w1 = Whh[j * 128 + k0 + 1];
            float l0 = w0 - __half2float(__float2half_rn(w0));
            float l1 = w1 - __half2float(__float2half_rn(w1));
            g_wlofrag[t * 8 + 2 * s + r] = packh2(l0, l1);
        }
    }
    g_wlofrag[t * 8 + 6] = 0u;
    g_wlofrag[t * 8 + 7] = 0u;
}

__global__ void __launch_bounds__(NT, 1)
gru_mma_kernel(const float* __restrict__ pm,
               const float* __restrict__ Wih,
               const float* __restrict__ Whh,
               const float* __restrict__ bih_g,
               const float* __restrict__ bhh_g,
               const float* __restrict__ fcw_g,
               const float* __restrict__ fcb_g,
               float* __restrict__ out)
{
    extern __shared__ char smem[];
    const uint32_t smb = smem_u32(smem);
    const int tid = threadIdx.x;
    const int lane = tid & 31;
    const int w = tid >> 5;
    const int bid80 = blockIdx.x * M_CTA;

    float* w0s   = (float*)(smem + SM_W0);
    float* w1s   = (float*)(smem + SM_W1);
    float* bss   = (float*)(smem + SM_BS);
    float* fcws  = (float*)(smem + SM_FCW);
    float* pmrow = (float*)(smem + SM_PMROW);
    float* xrow  = (float*)(smem + SM_XROW);
    int*   csrow = (int*)  (smem + SM_CSROW);
    float* xpart = (float*)(smem + SM_XPART);
    float* hst   = (float*)(smem + SM_HST);

    // stage Whi (fp16, swizzled): addr = j*256 + (((k>>3)^(j&7))<<4) + (k&7)*2
    {
        const float4* Wg = (const float4*)Whh;
        for (int v = tid; v < 384 * 32; v += NT) {
            int j = v >> 5, k4 = (v & 31) * 4;
            float4 wv = Wg[v];
            uint32_t off = (uint32_t)(j * 256 + ((((k4 >> 3) ^ (j & 7))) << 4) + (k4 & 7) * 2);
            *(uint2*)(smem + SM_WHI + off) =
                make_uint2(packh2(wv.x, wv.y), packh2(wv.z, wv.w));
        }
    }
    for (int v = tid; v < 32768 / 8; v += NT)
        ((uint2*)(smem + SM_AHI))[v] = make_uint2(0u, 0u);
    for (int v = tid; v < 80 * HSTRIDE; v += NT)
        hst[v] = 0.f;

    for (int i = tid; i < 384; i += NT) { w0s[i] = Wih[2 * i]; w1s[i] = Wih[2 * i + 1]; }
    if (tid < 128) {
        bss[tid]       = bih_g[tid]       + bhh_g[tid];         // r
        bss[128 + tid] = bih_g[128 + tid] + bhh_g[128 + tid];   // z
        bss[256 + tid] = bih_g[256 + tid];                       // i_n bias
        bss[384 + tid] = bhh_g[256 + tid];                       // h_n bias
        fcws[tid] = fcw_g[tid];
    }
    if (tid < M_CTA) {
        int s = bid80 + tid;
        bool v = s < SEQ;
        int ss = v ? s : 0;
        int b = ss / NNN, n = ss % NNN;
        csrow[tid] = b * TT * NNN + n;
        pmrow[tid] = v ? pm[b * TT * NNN + n] : 0.f;
        xrow[tid] = 0.f;
    }
    __syncthreads();

    // lane roles
    const int lx7 = lane & 7;
    const int rA  = (lane & 7) + ((lane >> 3) & 1) * 8;
    const int cA  = lane >> 4;
    const int cB  = (lane >> 3) & 1;
    const int q   = lane >> 2, p4 = lane & 3;

    const uint32_t wA4 = smb + SM_WHI
        + (uint32_t)((8 * w + (lane & 7) + (((lane >> 4) & 1) << 7)) * 256);
    const uint32_t wA2 = smb + SM_WHI
        + (uint32_t)((8 * w + 256 + (lane & 7)) * 256);
    uint32_t aAddr[5];
#pragma unroll
    for (int mt = 0; mt < 5; mt++)
        aAddr[mt] = smb + SM_AHI + (uint32_t)((16 * mt + rA) * 256);

    const uint4* wloP = (const uint4*)(g_wlofrag) + (size_t)((w * 32 + lane) * 8) * 2;
    const float fcb = fcb_g[0];
    const int c0 = 8 * w + 2 * p4;

    for (int t = 0; t < TT; t++) {
        float acc[3][5][4];
#pragma unroll
        for (int g = 0; g < 3; g++)
#pragma unroll
            for (int mt = 0; mt < 5; mt++)
#pragma unroll
                for (int e = 0; e < 4; e++) acc[g][mt][e] = 0.f;

        // 2 passes fused per K: Ahi x Whi + Ahi x Wlo (Wlo prefetched distance-1)
        uint4 pf1 = __ldg(wloP);
        uint2 pf2 = __ldg((const uint2*)(wloP + 1));
#pragma unroll
        for (int K = 0; K < 8; K++) {
            uint32_t bl[3][2];
            bl[0][0] = pf1.x; bl[0][1] = pf1.y;
            bl[1][0] = pf1.z; bl[1][1] = pf1.w;
            bl[2][0] = pf2.x; bl[2][1] = pf2.y;
            if (K < 7) {
                pf1 = __ldg(wloP + (K + 1) * 2);
                pf2 = __ldg((const uint2*)(wloP + (K + 1) * 2 + 1));
            }
            const uint32_t offA = (uint32_t)(((2 * K + cA) ^ lx7) << 4);
            uint32_t a[5][4];
#pragma unroll
            for (int mt = 0; mt < 5; mt++)
                LDSM4(a[mt][0], a[mt][1], a[mt][2], a[mt][3], aAddr[mt] + offA);
            const uint32_t offW = (uint32_t)(((2 * K + cB) ^ lx7) << 4);
            uint32_t bh[3][2];
            LDSM4(bh[0][0], bh[0][1], bh[1][0], bh[1][1], wA4 + offW);
            LDSM2(bh[2][0], bh[2][1], wA2 + offW);
#pragma unroll
            for (int g = 0; g < 3; g++)
#pragma unroll
                for (int mt = 0; mt < 5; mt++) {
                    MMA16816(acc[g][mt], a[mt], bh[g]);
                    MMA16816(acc[g][mt], a[mt], bl[g]);
                }
        }
        __syncthreads();   // B1: A reads done; also publishes xrow/pmrow(t)

        // ---- epilogue ----
        float w0r[2], w1r[2], br[2], w0z[2], w1z[2], bz[2],
              w0n[2], w1n[2], bi_n[2], bh_n[2], fc[2];
#pragma unroll
        for (int e = 0; e < 2; e++) {
            const int c = c0 + e;
            w0r[e] = w0s[c];       w1r[e] = w1s[c];       br[e] = bss[c];
            w0z[e] = w0s[128 + c]; w1z[e] = w1s[128 + c]; bz[e] = bss[128 + c];
            w0n[e] = w0s[256 + c]; w1n[e] = w1s[256 + c];
            bi_n[e] = bss[256 + c]; bh_n[e] = bss[384 + c];
            fc[e] = fcws[c];
        }

        float px[10];
#pragma unroll
        for (int i = 0; i < 10; i++) px[i] = 0.f;

#pragma unroll
        for (int mt = 0; mt < 5; mt++)
#pragma unroll
            for (int hf = 0; hf < 2; hf++) {
                const int row = 16 * mt + 8 * hf + q;
                const float xm = xrow[row], pv = pmrow[row];
                float2 ho2 = *(float2*)(hst + row * HSTRIDE + c0);
                const int r0i = hf * 2, r1i = hf * 2 + 1;

                const float gr0 = acc[0][mt][r0i] + fmaf(w0r[0], xm, fmaf(w1r[0], pv, br[0]));
                const float gr1 = acc[0][mt][r1i] + fmaf(w0r[1], xm, fmaf(w1r[1], pv, br[1]));
                const float gz0 = acc[1][mt][r0i] + fmaf(w0z[0], xm, fmaf(w1z[0], pv, bz[0]));
                const float gz1 = acc[1][mt][r1i] + fmaf(w0z[1], xm, fmaf(w1z[1], pv, bz[1]));
                // batched sigmoids: one rcp for 4 denominators
                const float dr0 = 1.f + __expf(-gr0);
                const float dr1 = 1.f + __expf(-gr1);
                const float dz0 = 1.f + __expf(-gz0);
                const float dz1 = 1.f + __expf(-gz1);
                const float m0 = dr0 * dr1, m1 = dz0 * dz1;
                const float rp = frcp(m0 * m1);
                const float r_0 = (dr1 * m1) * rp;
                const float r_1 = (dr0 * m1) * rp;
                const float z_0 = (m0 * dz1) * rp;
                const float z_1 = (m0 * dz0) * rp;

                const float a0 = fmaf(w0n[0], xm, fmaf(w1n[0], pv, bi_n[0]))
                               + r_0 * (acc[2][mt][r0i] + bh_n[0]);
                const float a1 = fmaf(w0n[1], xm, fmaf(w1n[1], pv, bi_n[1]))
                               + r_1 * (acc[2][mt][r1i] + bh_n[1]);
                // batched tanh: one rcp for both denominators
                const float dn0 = 1.f + __expf(2.f * a0);
                const float dn1 = 1.f + __expf(2.f * a1);
                const float rq = frcp(dn0 * dn1);
                const float nt0 = fmaf(-2.f, dn1 * rq, 1.f);
                const float nt1 = fmaf(-2.f, dn0 * rq, 1.f);

                const float hn0 = nt0 + z_0 * (ho2.x - nt0);
                const float hn1 = nt1 + z_1 * (ho2.y - nt1);
                px[mt * 2 + hf] = fmaf(hn0, fc[0], fmaf(hn1, fc[1], px[mt * 2 + hf]));

                *(float2*)(hst + row * HSTRIDE + c0) = make_float2(hn0, hn1);
                if (bid80 + row < SEQ)
                    *(float2*)(out + (size_t)(csrow[row] + t * NNN) * 128 + c0)
                        = make_float2(hn0, hn1);
                // write h_new back to A smem as fp16 (swizzled)
                const uint32_t aoff = (uint32_t)(row * 256 + ((w ^ q) << 4) + 4 * p4);
                *(uint32_t*)(smem + SM_AHI + aoff) = packh2(hn0, hn1);
            }

        // fc partials: sum over p4 lanes, stash per-warp
#pragma unroll
        for (int rr = 0; rr < 10; rr++) {
            float v = px[rr];
            v += __shfl_xor_sync(0xFFFFFFFFu, v, 1);
            v += __shfl_xor_sync(0xFFFFFFFFu, v, 2);
            if (p4 == 0)
                xpart[w * 80 + 16 * (rr >> 1) + 8 * (rr & 1) + q] = v;
        }
        __syncthreads();   // B2: A writes + xpart visible

        // x_{t+1}; published to other threads by next iteration's B1
        if (tid < M_CTA) {
            float sx = fcb;
#pragma unroll
            for (int ww = 0; ww < 16; ww++) sx += xpart[ww * 80 + tid];
            xrow[tid] = sx;
            const int s = bid80 + tid;
            const bool v = s < SEQ;
            if (t + 1 < TT) pmrow[tid] = v ? pm[csrow[tid] + (t + 1) * NNN] : 0.f;
            if (t == TT - 1 && v) out[H_ELEMS + (size_t)s] = sx;
        }
    }
}

extern "C" void kernel_launch(void* const* d_in, const int* in_sizes, int n_in,
                              void* d_out, int out_size) {
    (void)in_sizes; (void)n_in; (void)out_size;
    const float* pm  = (const float*)d_in[0];
    const float* Wih = (const float*)d_in[1];
    const float* Whh = (const float*)d_in[2];
    const float* bih = (const float*)d_in[3];
    const float* bhh = (const float*)d_in[4];
    const float* fcw = (const float*)d_in[5];
    const float* fcb = (const float*)d_in[6];
    float* out = (float*)d_out;

    pack_wlo_kernel<<<16, 256>>>(Whh);
    cudaFuncSetAttribute(gru_mma_kernel,
                         cudaFuncAttributeMaxDynamicSharedMemorySize,
                         SMEM_BYTES);
    gru_mma_kernel<<<GRIDX, NT, SMEM_BYTES>>>(
        pm, Wih, Whh, bih, bhh, fcw, fcb, out);
}